// round 6
// baseline (speedup 1.0000x reference)
#include <cuda_runtime.h>
#include <cstdint>

// FSMN depthwise strided FIR on GB300 — R6.
// vs R5 (79.9us): LDS-crossbar traffic was the binding resource
// (~2944 cyc/block-tile vs 2624 FMA). Raise reuse: RT=16 outputs per thread
// per stream => window loads per output drop 3.5 -> 2.25 per stream (-36%
// crossbar). Register fit: each thread owns ONE parity (512-thread block,
// 32 dp x 8 groups x 2 par), so acc[16]+w[16]+taps[21] ~ 106 u64-regs peak.
// Tile TT=256 outputs, smem 336x32 u64 = 86KB, double-buffered cp.async
// (172KB/SM), block persistent over 2 tiles.
//
// out[b,t,d] = sum_{i=0..19} filt[i,d]*x[b,t-(20-i)*2,d]
//            + filt[20,d]*x[b,t,d]
//            + sum_{j=0..19} filt[21+j,d]*x[b,t+1+2j,d],  zero-padded.

#define B_   32
#define T_   2000
#define DPAL 256        // d-pairs across all of D
#define DPB  32         // d-pairs per block
#define RT   16         // outputs per thread (one parity)
#define TT   256        // t-outputs per tile (8 groups x 32)
#define TPB  2          // tiles per block (8 tiles total per (b,slab))
#define ROWS (TT + 80)  // 336 smem rows per tile
#define STRIDE (ROWS * DPB)            // u64 per buffer
#define SMEM_BYTES (2 * STRIDE * 8)    // 172032 B
#define CHUNKS (ROWS * 16)             // 16B units per tile = 5376

__device__ __forceinline__ uint64_t f2fma(uint64_t a, uint64_t b, uint64_t c) {
    uint64_t r;
    asm("fma.rn.f32x2 %0, %1, %2, %3;" : "=l"(r) : "l"(a), "l"(b), "l"(c));
    return r;
}

__device__ __forceinline__ uint32_t smem_u32(const void* p) {
    uint32_t a;
    asm("{ .reg .u64 t; cvta.to.shared.u64 t, %1; cvt.u32.u64 %0, t; }"
        : "=r"(a) : "l"(p));
    return a;
}

__global__ __launch_bounds__(512, 1)
void fsmn_kernel(const float* __restrict__ x,
                 const float* __restrict__ filt,
                 float* __restrict__ out)
{
    extern __shared__ uint64_t sx[];   // [2][ROWS][DPB]

    const int tid = threadIdx.x;
    const int q0  = blockIdx.x * TPB;         // first tile index
    const int dpg = blockIdx.y * DPB;         // d-pair base
    const int b   = blockIdx.z;

    const uint64_t* __restrict__ xg =
        reinterpret_cast<const uint64_t*>(x) + (size_t)b * T_ * DPAL + dpg;
    uint64_t* __restrict__ og =
        reinterpret_cast<uint64_t*>(out) + (size_t)b * T_ * DPAL + dpg;

    const uint32_t sbase = smem_u32(sx);

    // -------- cp.async tile prefetch: 5376 16B units, ~10.5 per thread ------
    auto prefetch = [&](int buf, int qt) {
        const int tb = qt * TT;
        const uint32_t db = sbase + (uint32_t)buf * (STRIDE * 8);
#pragma unroll
        for (int k = 0; k < 11; ++k) {
            const int u = tid + k * 512;
            if (u < CHUNKS) {
                const int row = u >> 4;
                const int c16 = u & 15;
                const int t   = tb - 40 + row;
                const char* gp =
                    reinterpret_cast<const char*>(xg + (size_t)t * DPAL)
                    + c16 * 16;
                const uint32_t dst = db + (uint32_t)(row * DPB) * 8 + c16 * 16;
                const int ok = (t >= 0 && t < T_) ? 16 : 0;
                asm volatile("cp.async.cg.shared.global [%0], [%1], 16, %2;"
                             :: "r"(dst), "l"(gp), "r"(ok) : "memory");
            }
        }
        asm volatile("cp.async.commit_group;" ::: "memory");
    };

    const int dpl = tid & (DPB - 1);          // 0..31
    const int par = (tid >> 5) & 1;           // parity owned by this thread
    const int g   = tid >> 6;                 // 0..7, 32 t each
    const uint64_t* __restrict__ fdp =
        reinterpret_cast<const uint64_t*>(filt) + dpg + dpl;

    prefetch(0, q0);

#pragma unroll
    for (int i = 0; i < TPB; ++i) {
        if (i < TPB - 1) {
            prefetch((i + 1) & 1, q0 + i + 1);
            asm volatile("cp.async.wait_group 1;" ::: "memory");
        } else {
            asm volatile("cp.async.wait_group 0;" ::: "memory");
        }
        __syncthreads();

        const int tb = (q0 + i) * TT;
        const uint64_t* __restrict__ sxp = sx + (i & 1) * STRIDE + dpl;
        const int rb0 = g * 32 + par;          // smem row of x[t0-40]

        uint64_t acc[RT];
#pragma unroll
        for (int r = 0; r < RT; ++r) acc[r] = 0ull;

        // ======== A phase: left taps filt[0..20] ========
        {
            uint64_t fL[21];
#pragma unroll
            for (int c = 0; c < 21; ++c) fL[c] = fdp[(size_t)c * DPAL];

            uint64_t w[RT];
#pragma unroll
            for (int u = 0; u < RT; ++u)
                w[u] = sxp[(rb0 + 2 * u) * DPB];
#pragma unroll
            for (int c = 0; c < 21; ++c) {
#pragma unroll
                for (int r = 0; r < RT; ++r)
                    acc[r] = f2fma(fL[c], w[(c + r) & (RT - 1)], acc[r]);
                if (c < 20)
                    w[c & (RT - 1)] = sxp[(rb0 + 2 * (c + RT)) * DPB];
            }
        }

        // ======== B phase: right taps filt[21..40] ========
        {
            uint64_t fR[20];
#pragma unroll
            for (int c = 0; c < 20; ++c) fR[c] = fdp[(size_t)(21 + c) * DPAL];

            const int rbB = rb0 + 41;          // smem row of x[t0+1]
            uint64_t w[RT];
#pragma unroll
            for (int u = 0; u < RT; ++u)
                w[u] = sxp[(rbB + 2 * u) * DPB];
#pragma unroll
            for (int c = 0; c < 20; ++c) {
#pragma unroll
                for (int r = 0; r < RT; ++r)
                    acc[r] = f2fma(fR[c], w[(c + r) & (RT - 1)], acc[r]);
                if (c < 19)
                    w[c & (RT - 1)] = sxp[(rbB + 2 * (c + RT)) * DPB];
            }
        }

        // -------- store 16 outputs (guard: last tile reaches t=2047) --------
        {
            const int t0 = tb + g * 32 + par;
#pragma unroll
            for (int r = 0; r < RT; ++r) {
                const int t = t0 + 2 * r;
                if (t < T_) og[(size_t)t * DPAL + dpl] = acc[r];
            }
        }
        __syncthreads();   // protect buf[i&1] before next prefetch
    }
}

extern "C" void kernel_launch(void* const* d_in, const int* in_sizes, int n_in,
                              void* d_out, int out_size)
{
    const float* x    = (const float*)d_in[0];   // [32, 2000, 512] f32
    const float* filt = (const float*)d_in[1];   // [41, 512] f32
    float* out        = (float*)d_out;           // [32, 2000, 512] f32

    cudaFuncSetAttribute(fsmn_kernel,
                         cudaFuncAttributeMaxDynamicSharedMemorySize,
                         SMEM_BYTES);

    dim3 grid(4,            // 4 groups x TPB=2 tiles -> 8 t-tiles (2048 >= 2000)
              DPAL / DPB,   // 8 d-pair slabs
              B_);          // 32 batch
    fsmn_kernel<<<grid, 512, SMEM_BYTES>>>(x, filt, out);
}

// round 7
// speedup vs baseline: 1.0015x; 1.0015x over previous
#include <cuda_runtime.h>
#include <cstdint>

// FSMN depthwise strided FIR on GB300 — R7.
// Base = R5 (79.9us, best). Two fixes:
//  (1) window ring 8 -> 10 with refill issued 2 iterations ahead of first use
//      (32 issue-cyc distance >= 29 cyc LDS latency; was 16 cyc -> ~13 cyc
//      exposed per refill, ~70 refills/thread/tile).
//  (2) register relief: one parity at a time (acc[8]) and taps via a depth-4
//      global->reg prefetch pipeline (L1-resident) instead of fL[21]/fR[20]
//      register arrays. ~90 regs vs hard 128 cap.
//
// out[b,t,d] = sum_{i=0..19} filt[i,d]*x[b,t-(20-i)*2,d]
//            + filt[20,d]*x[b,t,d]
//            + sum_{j=0..19} filt[21+j,d]*x[b,t+1+2j,d],  zero-padded.

#define B_   32
#define T_   2000
#define DPAL 256        // d-pairs across all of D
#define DPB  32         // d-pairs per block
#define RT   8          // outputs per parity chunk
#define RING 10         // window ring (distance-2 refills)
#define TT   128        // t-outputs per tile
#define TPB  4          // tiles per block; grid.x=4 -> 16 tiles
#define ROWS (TT + 80)  // 208 smem rows per tile
#define STRIDE (ROWS * DPB)            // u64 per buffer
#define SMEM_BYTES (2 * STRIDE * 8)    // 106496 B

__device__ __forceinline__ uint64_t f2fma(uint64_t a, uint64_t b, uint64_t c) {
    uint64_t r;
    asm("fma.rn.f32x2 %0, %1, %2, %3;" : "=l"(r) : "l"(a), "l"(b), "l"(c));
    return r;
}

__device__ __forceinline__ uint32_t smem_u32(const void* p) {
    uint32_t a;
    asm("{ .reg .u64 t; cvta.to.shared.u64 t, %1; cvt.u32.u64 %0, t; }"
        : "=r"(a) : "l"(p));
    return a;
}

// One dense stream: NT taps, rows rb+2l in smem, taps ft[0..NT-1] at
// ft_base[c*DPAL]. Ring of RING=10 rows; refill row c+9 issued at iter c
// (slot (c+9)%10 freed after iter c-1), first consumed at iter c+2.
template<int NT>
__device__ __forceinline__ void stream_acc(uint64_t* __restrict__ acc,
                                           const uint64_t* __restrict__ sxp,
                                           int rb,
                                           const uint64_t* __restrict__ ftb)
{
    uint64_t tp[4];
#pragma unroll
    for (int k = 0; k < 4; ++k) tp[k] = ftb[(size_t)k * DPAL];

    uint64_t w[RING];
#pragma unroll
    for (int l = 0; l < RING; ++l) w[l] = sxp[(rb + 2 * l) * DPB];

#pragma unroll
    for (int c = 0; c < NT; ++c) {
        if (c >= 1 && c + 9 <= NT + 6)
            w[(c + 9) % RING] = sxp[(rb + 2 * (c + 9)) * DPB];
        const uint64_t tap = tp[c & 3];
        if (c + 4 < NT) tp[c & 3] = ftb[(size_t)(c + 4) * DPAL];
#pragma unroll
        for (int r = 0; r < RT; ++r)
            acc[r] = f2fma(tap, w[(c + r) % RING], acc[r]);
    }
}

__global__ __launch_bounds__(256, 2)
void fsmn_kernel(const float* __restrict__ x,
                 const float* __restrict__ filt,
                 float* __restrict__ out)
{
    extern __shared__ uint64_t sx[];   // [2][ROWS][DPB]

    const int tid = threadIdx.x;
    const int q0  = blockIdx.x * TPB;         // first tile index
    const int dpg = blockIdx.y * DPB;         // d-pair base
    const int b   = blockIdx.z;

    const uint64_t* __restrict__ xg =
        reinterpret_cast<const uint64_t*>(x) + (size_t)b * T_ * DPAL + dpg;
    uint64_t* __restrict__ og =
        reinterpret_cast<uint64_t*>(out) + (size_t)b * T_ * DPAL + dpg;

    const uint32_t sbase = smem_u32(sx);

    // -------- cp.async tile prefetch: 3328 16B units, 13 per thread --------
    auto prefetch = [&](int buf, int qt) {
        const int tb = qt * TT;
        const uint32_t db = sbase + (uint32_t)buf * (STRIDE * 8);
#pragma unroll
        for (int k = 0; k < 13; ++k) {
            const int u   = tid + k * 256;
            const int row = u >> 4;
            const int c16 = u & 15;
            const int t   = tb - 40 + row;
            const char* gp = reinterpret_cast<const char*>(xg + (size_t)t * DPAL)
                             + c16 * 16;
            const uint32_t dst = db + (uint32_t)(row * DPB) * 8 + c16 * 16;
            const int ok = (t >= 0 && t < T_) ? 16 : 0;
            asm volatile("cp.async.cg.shared.global [%0], [%1], 16, %2;"
                         :: "r"(dst), "l"(gp), "r"(ok) : "memory");
        }
        asm volatile("cp.async.commit_group;" ::: "memory");
    };

    const int dpl = tid & (DPB - 1);          // 0..31
    const int g   = tid >> 5;                 // 0..7 (16 t each)
    const uint64_t* __restrict__ fdp =
        reinterpret_cast<const uint64_t*>(filt) + dpg + dpl;

    prefetch(0, q0);

#pragma unroll
    for (int i = 0; i < TPB; ++i) {
        if (i < TPB - 1) {
            prefetch((i + 1) & 1, q0 + i + 1);
            asm volatile("cp.async.wait_group 1;" ::: "memory");
        } else {
            asm volatile("cp.async.wait_group 0;" ::: "memory");
        }
        __syncthreads();

        const int tb = (q0 + i) * TT;
        const uint64_t* __restrict__ sxp = sx + (i & 1) * STRIDE + dpl;

#pragma unroll
        for (int par = 0; par < 2; ++par) {
            const int rb = g * 16 + par;       // smem row of x[t0-40]

            uint64_t acc[RT];
#pragma unroll
            for (int r = 0; r < RT; ++r) acc[r] = 0ull;

            // A stream: left+center taps filt[0..20] over x[t0-40+2l]
            stream_acc<21>(acc, sxp, rb, fdp);
            // B stream: right taps filt[21..40] over x[t0+1+2l]
            stream_acc<20>(acc, sxp, rb + 41, fdp + (size_t)21 * DPAL);

            // store 8 outputs (guard: last tile reaches t=2047)
            const int t0 = tb + g * 16 + par;
#pragma unroll
            for (int r = 0; r < RT; ++r) {
                const int t = t0 + 2 * r;
                if (t < T_) og[(size_t)t * DPAL + dpl] = acc[r];
            }
        }
        __syncthreads();   // protect buf[i&1] before next prefetch
    }
}

extern "C" void kernel_launch(void* const* d_in, const int* in_sizes, int n_in,
                              void* d_out, int out_size)
{
    const float* x    = (const float*)d_in[0];   // [32, 2000, 512] f32
    const float* filt = (const float*)d_in[1];   // [41, 512] f32
    float* out        = (float*)d_out;           // [32, 2000, 512] f32

    cudaFuncSetAttribute(fsmn_kernel,
                         cudaFuncAttributeMaxDynamicSharedMemorySize,
                         SMEM_BYTES);

    dim3 grid(4,            // 4 groups x TPB=4 tiles -> 16 t-tiles
              DPAL / DPB,   // 8 d-pair slabs
              B_);          // 32 batch
    fsmn_kernel<<<grid, 256, SMEM_BYTES>>>(x, filt, out);
}